// round 16
// baseline (speedup 1.0000x reference)
#include <cuda_runtime.h>
#include <cstdint>

#define NFEAT 784
#define NCLS  10
#define KC    16
#define NT    49                     // 784 / 16
#define TPB   448                    // 14 warps
#define NWARP 14
#define ROWSPW 32                    // rows per warp
#define ROWSPC (NWARP * ROWSPW)      // 448 rows per CTA -> grid 147
#define XSTR  16                     // floats per row slot
#define SLOTF (ROWSPW * XSTR)        // 512 floats = 2KB per tile slot
#define SLOT_BYTES (SLOTF * 4)
#define NBUF  4                      // warp-private ring depth
#define RINGF (NBUF * SLOTF)         // 2048 floats per warp
#define XS_FLOATS (NWARP * RINGF)    // 28672
#define AS_FLOATS (NCLS * NFEAT)     // 7840
#define RED_FLOATS (NWARP * NCLS)    // 140
#define SMEM_FLOATS (XS_FLOATS + AS_FLOATS + RED_FLOATS + 2)
#define SMEM_BYTES  (SMEM_FLOATS * 4)    // ~146.6 KB -> 1 CTA/SM

// ---------------------------------------------------------------------------
__device__ __forceinline__ void cp_async16(uint32_t saddr, const void* gptr) {
    asm volatile("cp.async.cg.shared.global [%0], [%1], 16;\n"
                 :: "r"(saddr), "l"(gptr));
}
#define CP_COMMIT() asm volatile("cp.async.commit_group;\n" ::: "memory")
#define CP_WAIT(n)  asm volatile("cp.async.wait_group %0;\n" :: "n"(n) : "memory")
#define FMA_F32X2(d, a, b) \
    asm volatile("fma.rn.f32x2 %0, %1, %2, %0;" : "+l"(d) : "l"(a), "l"(b))

extern __shared__ float smem[];

// ---------------------------------------------------------------------------
// R15 layout + strength-reduced addressing: producer uses induction pointers
// (4 IADD/tile), t-loop unrolled by NBUF so ring-slot offsets are immediates.
// Lane = (sr, kg): owns rows {sr+8*ri} and k-slice kg*4..kg*4+3; one warp-wide
// LDS.128 of A per class (4 distinct 16B slices). Barrier-free mainloop.
// ---------------------------------------------------------------------------
__global__ void __launch_bounds__(TPB, 1)
fused_kernel(const float* __restrict__ x,
             const float* __restrict__ W,
             const float* __restrict__ Bsp,
             const float* __restrict__ fcw,
             const float* __restrict__ fcb,
             float* __restrict__ out, int Brows)
{
    float* As  = smem + XS_FLOATS;            // [10][784] class-contiguous
    float* red = As + AS_FLOATS;              // [14][10]

    const int tid  = threadIdx.x;
    const int wid  = tid >> 5;
    const int lane = tid & 31;
    const int sr   = lane >> 2;               // sub-row 0..7
    const int kg   = lane & 3;                // k-group 0..3
    const int wrow0 = blockIdx.x * ROWSPC + wid * ROWSPW;
    float* xw = smem + wid * RINGF;

    // ---- producer induction state: 4 (gmem ptr, smem base) pairs per lane ----
    const float* gp[4];
    uint32_t sa0[4];
#pragma unroll
    for (int i = 0; i < 4; ++i) {
        int g  = lane + i * 32;               // (row, 16B-chunk)
        int r  = g >> 2;
        int ch = g & 3;
        int row = wrow0 + r;
        if (row >= Brows) row = Brows - 1;    // clamp (reads discarded)
        gp[i]  = x + (size_t)row * NFEAT + ch * 4;
        sa0[i] = (uint32_t)__cvta_generic_to_shared(xw + r * XSTR + ch * 4);
    }

#define ISSUE_TILE(slot)                                   \
    do {                                                   \
        _Pragma("unroll")                                  \
        for (int i = 0; i < 4; ++i) {                      \
            cp_async16(sa0[i] + (slot) * SLOT_BYTES, gp[i]); \
            gp[i] += KC;                                   \
        }                                                  \
        CP_COMMIT();                                       \
    } while (0)

    // Kick DRAM immediately: 3 tiles in flight per warp while A is built.
    ISSUE_TILE(0);
    ISSUE_TILE(1);
    ISSUE_TILE(2);

    // ---- build A[c][k] and per-warp bias partials in shared ----
    float part[NCLS];
#pragma unroll
    for (int c = 0; c < NCLS; ++c) part[c] = 0.f;

    for (int k = tid; k < NFEAT; k += TPB) {
        // scatter column map (faithful to the reference's i=782 wraparound bug)
        int c0i = (k == NFEAT - 2) ? 0 : k;
        int c1i = (k == NFEAT - 2) ? 1 : ((k + 1 == NFEAT) ? 0 : k + 1);
        float w0 = W[2*k],   w1 = W[2*k+1];
        float b0 = Bsp[2*k], b1 = Bsp[2*k+1];
#pragma unroll
        for (int c = 0; c < NCLS; ++c) {
            float f0 = __ldg(fcw + c * NFEAT + c0i);
            float f1 = __ldg(fcw + c * NFEAT + c1i);
            As[c * NFEAT + k] = f0 * w0 + f1 * w1;
            part[c] += f0 * b0 + f1 * b1;
        }
    }
#pragma unroll
    for (int off = 16; off; off >>= 1)
#pragma unroll
        for (int c = 0; c < NCLS; ++c)
            part[c] += __shfl_down_sync(0xffffffffu, part[c], off);
    if (lane == 0)
#pragma unroll
        for (int c = 0; c < NCLS; ++c) red[wid * NCLS + c] = part[c];
    __syncthreads();     // the ONLY barrier: A + red visible to all warps

    // ---- barrier-free main loop, unrolled x4 so slots are immediates ----
    unsigned long long acc[NCLS * 4];         // [c][ri]
#pragma unroll
    for (int i = 0; i < NCLS * 4; ++i) acc[i] = 0ULL;

    const float* Ak = As + kg * 4;            // advances by KC per tile

#define CONSUME_TILE(slot)                                                    \
    do {                                                                      \
        const float* xb = xw + (slot) * SLOTF;                                \
        ulonglong2 xv[4];                                                     \
        _Pragma("unroll")                                                     \
        for (int ri = 0; ri < 4; ++ri)                                        \
            xv[ri] = *(const ulonglong2*)(xb + (sr + 8 * ri) * XSTR + kg * 4);\
        _Pragma("unroll")                                                     \
        for (int c = 0; c < NCLS; ++c) {                                      \
            ulonglong2 av = *(const ulonglong2*)(Ak + c * NFEAT);             \
            _Pragma("unroll")                                                 \
            for (int ri = 0; ri < 4; ++ri) {                                  \
                FMA_F32X2(acc[c * 4 + ri], xv[ri].x, av.x);                   \
                FMA_F32X2(acc[c * 4 + ri], xv[ri].y, av.y);                   \
            }                                                                 \
        }                                                                     \
        Ak += KC;                                                             \
    } while (0)

    // t = 0 .. 43 (11 groups of 4): steady state, WAIT(2), issue t+3
#pragma unroll 1
    for (int tq = 0; tq < 44; tq += 4) {
        CP_WAIT(2); CONSUME_TILE(0); ISSUE_TILE(3);
        CP_WAIT(2); CONSUME_TILE(1); ISSUE_TILE(0);
        CP_WAIT(2); CONSUME_TILE(2); ISSUE_TILE(1);
        CP_WAIT(2); CONSUME_TILE(3); ISSUE_TILE(2);
    }
    // t = 44..48 tail (issue 47, 48; drain)
    CP_WAIT(2); CONSUME_TILE(0); ISSUE_TILE(3);   // t=44, issue 47
    CP_WAIT(2); CONSUME_TILE(1); ISSUE_TILE(0);   // t=45, issue 48
    CP_WAIT(2); CONSUME_TILE(2);                  // t=46 (pending 46,47,48)
    CP_WAIT(1); CONSUME_TILE(3);                  // t=47
    CP_WAIT(0); CONSUME_TILE(0);                  // t=48

    // ---- epilogue: fold k-pairs + kg lanes, bias, softmax, store ----
    float c0v[NCLS];
#pragma unroll
    for (int c = 0; c < NCLS; ++c) {
        float s = __ldg(fcb + c);
#pragma unroll
        for (int w = 0; w < NWARP; ++w) s += red[w * NCLS + c];
        c0v[c] = s;
    }

    // lane (sr,kg) ends up owning row sr + 8*kg (takes ri == kg)
    float logit[NCLS];
#pragma unroll
    for (int c = 0; c < NCLS; ++c) {
#pragma unroll
        for (int ri = 0; ri < 4; ++ri) {
            unsigned long long a = acc[c * 4 + ri];
            float v = __uint_as_float((unsigned)(a & 0xffffffffu))
                    + __uint_as_float((unsigned)(a >> 32));
            v += __shfl_xor_sync(0xffffffffu, v, 1);
            v += __shfl_xor_sync(0xffffffffu, v, 2);
            if (ri == kg) logit[c] = v + c0v[c];
        }
    }

    float m = logit[0];
#pragma unroll
    for (int c = 1; c < NCLS; ++c) m = fmaxf(m, logit[c]);
    float ssum = 0.f;
#pragma unroll
    for (int c = 0; c < NCLS; ++c) { logit[c] = __expf(logit[c] - m); ssum += logit[c]; }
    float inv = 1.0f / ssum;

    const int row = wrow0 + sr + 8 * kg;
    if (row < Brows) {
        float2* po = (float2*)(out + (size_t)row * NCLS);
#pragma unroll
        for (int c = 0; c < NCLS; c += 2)
            po[c >> 1] = make_float2(logit[c] * inv, logit[c + 1] * inv);
    }
}

// ---------------------------------------------------------------------------
extern "C" void kernel_launch(void* const* d_in, const int* in_sizes, int n_in,
                              void* d_out, int out_size) {
    const float* x   = (const float*)d_in[0];
    const float* W   = (const float*)d_in[1];
    const float* bsp = (const float*)d_in[2];
    const float* fcw = (const float*)d_in[3];
    const float* fcb = (const float*)d_in[4];
    float* out = (float*)d_out;
    const int Brows = in_sizes[0] / NFEAT;

    cudaFuncSetAttribute(fused_kernel,
                         cudaFuncAttributeMaxDynamicSharedMemorySize, SMEM_BYTES);

    const int grid = (Brows + ROWSPC - 1) / ROWSPC;   // 147 for B=65536
    fused_kernel<<<grid, TPB, SMEM_BYTES>>>(x, W, bsp, fcw, fcb, out, Brows);
}